// round 5
// baseline (speedup 1.0000x reference)
#include <cuda_runtime.h>
#include <cuda_bf16.h>
#include <math.h>

// Problem dims (fixed)
#define B_  64
#define T_  512
#define E_  256
#define H_  256
#define O_  256
#define M_  (T_ * B_)          // 32768 rows (t-major, b-minor)

// Scan W_hh split: 160 rows (80 f32x2 pairs) in registers, 96 rows in shared (paired)
#define KREGP 80               // register pairs   (k = 0..159)
#define KSH2  24               // shared ulonglong2 groups of 4 rows (k = 160..255)
#define SMEM_SCAN ((2 * H_) * sizeof(float) + (KSH2 * H_) * sizeof(ulonglong2))

typedef unsigned long long u64;

// ---------------------------------------------------------------------------
// f32x2 packed-FMA helpers (sm_100a). pk2/upk2 only outside hot loops.
// ---------------------------------------------------------------------------
__device__ __forceinline__ u64 pk2(float lo, float hi) {
    u64 r;
    asm("mov.b64 %0, {%1, %2};" : "=l"(r) : "f"(lo), "f"(hi));
    return r;
}
__device__ __forceinline__ void upk2(u64 v, float& lo, float& hi) {
    asm("mov.b64 {%0, %1}, %2;" : "=f"(lo), "=f"(hi) : "l"(v));
}
#define FMA2(d, a, b, c) \
    asm("fma.rn.f32x2 %0, %1, %2, %3;" : "=l"(d) : "l"(a), "l"(b), "l"(c))

__device__ __forceinline__ float fast_tanh(float v) {
    float x = fminf(fmaxf(v, -15.f), 15.f);
    float e = __expf(2.f * x);
    return __fdividef(e - 1.f, e + 1.f);
}

// ---------------------------------------------------------------------------
// Static device scratch (no allocation allowed)
// ---------------------------------------------------------------------------
__device__ float g_xf[(size_t)T_ * B_ * H_];   // xf[t][b][j]   (32 MB)
__device__ float g_xb[(size_t)T_ * B_ * H_];   // xb[s][b][j], s = scan index (32 MB)
__device__ float g_h [(size_t)M_ * (2 * H_)];  // hcat[t*64+b][0:256]=hf, [256:512]=hb (64 MB)

// ---------------------------------------------------------------------------
// Kernel 1: fused input projections, FFMA2 with zero inner-loop MOVs.
// B fragments stored PRE-DUPLICATED in shared as u64 {w,w}.
// A fragments read as natural u64 pairs from As.
// ---------------------------------------------------------------------------
__global__ __launch_bounds__(256) void proj_kernel(
    const float* __restrict__ X,
    const float* __restrict__ Wf, const float* __restrict__ bfv,
    const float* __restrict__ Wb, const float* __restrict__ bbv)
{
    __shared__ float As [16][132];   // [k][m], padded, 8B-aligned rows (528B stride)
    __shared__ u64  Bfs2[16][68];    // [k][j] pre-duplicated pairs
    __shared__ u64  Bbs2[16][68];

    const int tid = threadIdx.x;
    const int m0 = blockIdx.y * 128;
    const int j0 = blockIdx.x * 64;

    const int rbase = (tid >> 4) * 8;     // 0..120 (even)
    const int cbase = (tid & 15) * 4;     // 0..60

    const int lr = tid >> 1;              // 0..127
    const int lc = (tid & 1) * 8;         // 0 or 8
    const int gm = m0 + lr;
    const float* arow = X + ((size_t)(gm & 63) * T_ + (gm >> 6)) * E_;

    const int bk = tid >> 4;              // 0..15
    const int bj = (tid & 15) * 4;        // 0..60

    u64 accf2[4][4], accb2[4][4];
    const u64 z2 = pk2(0.f, 0.f);
#pragma unroll
    for (int i = 0; i < 4; i++)
#pragma unroll
        for (int j = 0; j < 4; j++) { accf2[i][j] = z2; accb2[i][j] = z2; }

    for (int e0 = 0; e0 < E_; e0 += 16) {
        float4 a0 = *(const float4*)(arow + e0 + lc);
        float4 a1 = *(const float4*)(arow + e0 + lc + 4);
        float4 f4 = *(const float4*)(Wf + (size_t)(e0 + bk) * H_ + j0 + bj);
        float4 b4 = *(const float4*)(Wb + (size_t)(e0 + bk) * H_ + j0 + bj);
        __syncthreads();
        As[lc + 0][lr] = a0.x; As[lc + 1][lr] = a0.y;
        As[lc + 2][lr] = a0.z; As[lc + 3][lr] = a0.w;
        As[lc + 4][lr] = a1.x; As[lc + 5][lr] = a1.y;
        As[lc + 6][lr] = a1.z; As[lc + 7][lr] = a1.w;
        Bfs2[bk][bj + 0] = pk2(f4.x, f4.x);
        Bfs2[bk][bj + 1] = pk2(f4.y, f4.y);
        Bfs2[bk][bj + 2] = pk2(f4.z, f4.z);
        Bfs2[bk][bj + 3] = pk2(f4.w, f4.w);
        Bbs2[bk][bj + 0] = pk2(b4.x, b4.x);
        Bbs2[bk][bj + 1] = pk2(b4.y, b4.y);
        Bbs2[bk][bj + 2] = pk2(b4.z, b4.z);
        Bbs2[bk][bj + 3] = pk2(b4.w, b4.w);
        __syncthreads();
#pragma unroll
        for (int kk = 0; kk < 16; kk++) {
            u64 a2[4], f2[4], b2[4];
#pragma unroll
            for (int i2 = 0; i2 < 4; i2++)
                a2[i2] = *(const u64*)&As[kk][rbase + 2 * i2];
#pragma unroll
            for (int j = 0; j < 4; j++) { f2[j] = Bfs2[kk][cbase + j]; b2[j] = Bbs2[kk][cbase + j]; }
#pragma unroll
            for (int i2 = 0; i2 < 4; i2++)
#pragma unroll
                for (int j = 0; j < 4; j++) {
                    FMA2(accf2[i2][j], a2[i2], f2[j], accf2[i2][j]);
                    FMA2(accb2[i2][j], a2[i2], b2[j], accb2[i2][j]);
                }
        }
    }

    float acc_f[8][4], acc_b[8][4];
#pragma unroll
    for (int i2 = 0; i2 < 4; i2++)
#pragma unroll
        for (int j = 0; j < 4; j++) {
            upk2(accf2[i2][j], acc_f[2 * i2][j], acc_f[2 * i2 + 1][j]);
            upk2(accb2[i2][j], acc_b[2 * i2][j], acc_b[2 * i2 + 1][j]);
        }

#pragma unroll
    for (int i = 0; i < 8; i++) {
        const int m = m0 + rbase + i;
        const int t = m >> 6, b = m & 63;
        const int m2 = (T_ - 1 - t) * B_ + b;      // scan index slot for xb
        float4 vf, vb;
        vf.x = acc_f[i][0] + bfv[j0 + cbase + 0];
        vf.y = acc_f[i][1] + bfv[j0 + cbase + 1];
        vf.z = acc_f[i][2] + bfv[j0 + cbase + 2];
        vf.w = acc_f[i][3] + bfv[j0 + cbase + 3];
        vb.x = acc_b[i][0] + bbv[j0 + cbase + 0];
        vb.y = acc_b[i][1] + bbv[j0 + cbase + 1];
        vb.z = acc_b[i][2] + bbv[j0 + cbase + 2];
        vb.w = acc_b[i][3] + bbv[j0 + cbase + 3];
        *(float4*)&g_xf[(size_t)m  * H_ + j0 + cbase] = vf;
        *(float4*)&g_xb[(size_t)m2 * H_ + j0 + cbase] = vb;
    }
}

// ---------------------------------------------------------------------------
// Kernel 2: persistent per-(batch,direction) recurrent scan, zero-MOV FFMA2.
// h read as ulonglong2 (natural pairs); W reg pairs packed at init;
// shared W tail stored pre-paired.
// ---------------------------------------------------------------------------
extern __shared__ float smem_scan[];

__global__ __launch_bounds__(256) void scan_kernel(
    const float* __restrict__ Whh_f,
    const float* __restrict__ Whh_b,
    float* __restrict__ out)
{
    float*      h_sh = smem_scan;                         // [2][256]
    ulonglong2* Wsh2 = (ulonglong2*)(smem_scan + 2 * H_); // [KSH2][256]

    const int t   = threadIdx.x;
    const int dir = blockIdx.x >> 6;    // 0 = fwd, 1 = bwd
    const int b   = blockIdx.x & 63;

    const float* W    = dir ? Whh_b : Whh_f;
    const float* xarr = dir ? g_xb  : g_xf;

    // register W pairs: wreg[p] = {W[2p][t], W[2p+1][t]}, k = 0..159
    u64 wreg[KREGP];
#pragma unroll
    for (int p = 0; p < KREGP; p++)
        wreg[p] = pk2(W[(size_t)(2 * p) * H_ + t], W[(size_t)(2 * p + 1) * H_ + t]);
    // shared W tail, pre-paired: Wsh2[r][t] = {{W[160+4r],W[161+4r]},{W[162+4r],W[163+4r]}}
    for (int r = 0; r < KSH2; r++) {
        ulonglong2 w;
        w.x = pk2(W[(size_t)(160 + 4 * r + 0) * H_ + t], W[(size_t)(160 + 4 * r + 1) * H_ + t]);
        w.y = pk2(W[(size_t)(160 + 4 * r + 2) * H_ + t], W[(size_t)(160 + 4 * r + 3) * H_ + t]);
        Wsh2[r * H_ + t] = w;
    }
    h_sh[t] = 0.f;
    __syncthreads();

    const float* xp = xarr + (size_t)b * H_ + t;  // step stride = B_*H_
    float x_next = xp[0];
    float hlast = 0.f;
    int p = 0;

    const u64 z2 = pk2(0.f, 0.f);

    for (int s = 0; s < T_; ++s) {
        float x_cur = x_next;
        if (s + 1 < T_) x_next = xp[(size_t)(s + 1) * (B_ * H_)];

        const ulonglong2* hc2 = (const ulonglong2*)(h_sh + p * H_); // 16B-aligned
        u64 a0 = z2, a1 = z2, a2 = z2, a3 = z2;

        // register-resident W rows: k = 0..159 (40 LDS.128, broadcast)
#pragma unroll
        for (int q = 0; q < 40; q++) {
            ulonglong2 hv = hc2[q];
            if (q & 1) {
                FMA2(a2, hv.x, wreg[2 * q + 0], a2);
                FMA2(a3, hv.y, wreg[2 * q + 1], a3);
            } else {
                FMA2(a0, hv.x, wreg[2 * q + 0], a0);
                FMA2(a1, hv.y, wreg[2 * q + 1], a1);
            }
        }
        // shared-resident W rows: k = 160..255
#pragma unroll
        for (int r = 0; r < KSH2; r++) {
            ulonglong2 hv = hc2[40 + r];
            ulonglong2 wv = Wsh2[r * H_ + t];
            FMA2(a0, hv.x, wv.x, a0);
            FMA2(a1, hv.y, wv.y, a1);
        }

        float l0, u0, l1, u1, l2, u2, l3, u3;
        upk2(a0, l0, u0); upk2(a1, l1, u1);
        upk2(a2, l2, u2); upk2(a3, l3, u3);
        float sum = ((l0 + u0) + (l1 + u1)) + ((l2 + u2) + (l3 + u3)) + x_cur;
        float hn = fast_tanh(sum);

        h_sh[(p ^ 1) * H_ + t] = hn;

        const int t_orig = dir ? (T_ - 1 - s) : s;
        g_h[((size_t)(t_orig * B_ + b)) * (2 * H_) + dir * H_ + t] = hn;

        hlast = hn;
        p ^= 1;
        __syncthreads();
    }

    out[(size_t)B_ * T_ * O_ + (size_t)dir * (B_ * H_) + (size_t)b * H_ + t] = hlast;
}

// ---------------------------------------------------------------------------
// Kernel 3: output GEMM, FFMA2 zero-MOV (same scheme as proj).
// ---------------------------------------------------------------------------
__global__ __launch_bounds__(256) void out_kernel(
    const float* __restrict__ Why, const float* __restrict__ byv,
    float* __restrict__ out)
{
    __shared__ float As[16][132];
    __shared__ u64  Bs2[16][68];

    const int tid = threadIdx.x;
    const int m0 = blockIdx.y * 128;
    const int j0 = blockIdx.x * 64;

    const int rbase = (tid >> 4) * 8;
    const int cbase = (tid & 15) * 4;

    const int lr = tid >> 1;
    const int lc = (tid & 1) * 8;
    const float* arow = g_h + (size_t)(m0 + lr) * (2 * H_);

    const int bk = tid >> 4;
    const int bj = (tid & 15) * 4;

    u64 acc2[4][4];
    const u64 z2 = pk2(0.f, 0.f);
#pragma unroll
    for (int i = 0; i < 4; i++)
#pragma unroll
        for (int j = 0; j < 4; j++) acc2[i][j] = z2;

    for (int e0 = 0; e0 < 2 * H_; e0 += 16) {
        float4 a0 = *(const float4*)(arow + e0 + lc);
        float4 a1 = *(const float4*)(arow + e0 + lc + 4);
        float4 w4 = *(const float4*)(Why + (size_t)(e0 + bk) * O_ + j0 + bj);
        __syncthreads();
        As[lc + 0][lr] = a0.x; As[lc + 1][lr] = a0.y;
        As[lc + 2][lr] = a0.z; As[lc + 3][lr] = a0.w;
        As[lc + 4][lr] = a1.x; As[lc + 5][lr] = a1.y;
        As[lc + 6][lr] = a1.z; As[lc + 7][lr] = a1.w;
        Bs2[bk][bj + 0] = pk2(w4.x, w4.x);
        Bs2[bk][bj + 1] = pk2(w4.y, w4.y);
        Bs2[bk][bj + 2] = pk2(w4.z, w4.z);
        Bs2[bk][bj + 3] = pk2(w4.w, w4.w);
        __syncthreads();
#pragma unroll
        for (int kk = 0; kk < 16; kk++) {
            u64 a2[4], w2[4];
#pragma unroll
            for (int i2 = 0; i2 < 4; i2++)
                a2[i2] = *(const u64*)&As[kk][rbase + 2 * i2];
#pragma unroll
            for (int j = 0; j < 4; j++) w2[j] = Bs2[kk][cbase + j];
#pragma unroll
            for (int i2 = 0; i2 < 4; i2++)
#pragma unroll
                for (int j = 0; j < 4; j++)
                    FMA2(acc2[i2][j], a2[i2], w2[j], acc2[i2][j]);
        }
    }

    float acc[8][4];
#pragma unroll
    for (int i2 = 0; i2 < 4; i2++)
#pragma unroll
        for (int j = 0; j < 4; j++)
            upk2(acc2[i2][j], acc[2 * i2][j], acc[2 * i2 + 1][j]);

#pragma unroll
    for (int i = 0; i < 8; i++) {
        const int m = m0 + rbase + i;
        const int t = m >> 6, b = m & 63;
        float4 v;
        v.x = acc[i][0] + byv[j0 + cbase + 0];
        v.y = acc[i][1] + byv[j0 + cbase + 1];
        v.z = acc[i][2] + byv[j0 + cbase + 2];
        v.w = acc[i][3] + byv[j0 + cbase + 3];
        *(float4*)&out[((size_t)b * T_ + t) * O_ + j0 + cbase] = v;
    }
}

// ---------------------------------------------------------------------------
// launch
// ---------------------------------------------------------------------------
extern "C" void kernel_launch(void* const* d_in, const int* in_sizes, int n_in,
                              void* d_out, int out_size)
{
    const float* X    = (const float*)d_in[0];
    const float* Wxhf = (const float*)d_in[1];
    const float* Whhf = (const float*)d_in[2];
    const float* bf   = (const float*)d_in[3];
    const float* Wxhb = (const float*)d_in[4];
    const float* Whhb = (const float*)d_in[5];
    const float* bb   = (const float*)d_in[6];
    const float* Why  = (const float*)d_in[7];
    const float* by   = (const float*)d_in[8];
    float* out = (float*)d_out;

    cudaFuncSetAttribute(scan_kernel,
                         cudaFuncAttributeMaxDynamicSharedMemorySize,
                         (int)SMEM_SCAN);

    proj_kernel<<<dim3(4, 256), 256>>>(X, Wxhf, bf, Wxhb, bb);
    scan_kernel<<<128, 256, SMEM_SCAN>>>(Whhf, Whhb, out);
    out_kernel<<<dim3(4, 256), 256>>>(Why, by, out);
}

// round 6
// speedup vs baseline: 1.3388x; 1.3388x over previous
#include <cuda_runtime.h>
#include <cuda_bf16.h>
#include <math.h>

// Problem dims (fixed)
#define B_  64
#define T_  512
#define E_  256
#define H_  256
#define O_  256
#define M_  (T_ * B_)          // 32768 rows (t-major, b-minor)

// Scan W_hh split: 160 rows (80 f32x2 pairs) in registers, 96 rows in shared (paired)
#define KREGP 80               // register pairs   (k = 0..159)
#define KSH2  24               // shared ulonglong2 groups of 4 rows (k = 160..255)
#define SMEM_SCAN ((2 * H_) * sizeof(float) + (KSH2 * H_) * sizeof(ulonglong2))

// x prefetch depth (register ring) — covers ~3 steps of DRAM latency
#define XPF 4

typedef unsigned long long u64;

// ---------------------------------------------------------------------------
// f32x2 packed-FMA helpers (sm_100a)
// ---------------------------------------------------------------------------
__device__ __forceinline__ u64 pk2(float lo, float hi) {
    u64 r;
    asm("mov.b64 %0, {%1, %2};" : "=l"(r) : "f"(lo), "f"(hi));
    return r;
}
__device__ __forceinline__ void upk2(u64 v, float& lo, float& hi) {
    asm("mov.b64 {%0, %1}, %2;" : "=f"(lo), "=f"(hi) : "l"(v));
}
#define FMA2(d, a, b, c) \
    asm("fma.rn.f32x2 %0, %1, %2, %3;" : "=l"(d) : "l"(a), "l"(b), "l"(c))

__device__ __forceinline__ float fast_tanh(float v) {
    float x = fminf(fmaxf(v, -15.f), 15.f);
    float e = __expf(2.f * x);
    return __fdividef(e - 1.f, e + 1.f);
}

// ---------------------------------------------------------------------------
// Static device scratch (no allocation allowed)
// ---------------------------------------------------------------------------
__device__ float g_xf[(size_t)T_ * B_ * H_];   // xf[t][b][j]   (32 MB)
__device__ float g_xb[(size_t)T_ * B_ * H_];   // xb[s][b][j], s = scan index (32 MB)
__device__ float g_h [(size_t)M_ * (2 * H_)];  // hcat[t*64+b][0:256]=hf, [256:512]=hb (64 MB)

// ---------------------------------------------------------------------------
// Kernel 1: fused input projections (R3 version — measured 188us, fma=65%).
// FFMA2 with float4 B loads + register packs (alu pipe), natural A pairs.
// ---------------------------------------------------------------------------
__global__ __launch_bounds__(256) void proj_kernel(
    const float* __restrict__ X,
    const float* __restrict__ Wf, const float* __restrict__ bfv,
    const float* __restrict__ Wb, const float* __restrict__ bbv)
{
    __shared__ float As [16][132];  // [k][m], padded
    __shared__ float Bfs[16][68];   // [k][j], padded
    __shared__ float Bbs[16][68];

    const int tid = threadIdx.x;
    const int m0 = blockIdx.y * 128;
    const int j0 = blockIdx.x * 64;

    const int rbase = (tid >> 4) * 8;     // 0..120
    const int cbase = (tid & 15) * 4;     // 0..60

    const int lr = tid >> 1;              // 0..127
    const int lc = (tid & 1) * 8;         // 0 or 8
    const int gm = m0 + lr;
    const float* arow = X + ((size_t)(gm & 63) * T_ + (gm >> 6)) * E_;

    const int bk = tid >> 4;              // 0..15
    const int bj = (tid & 15) * 4;        // 0..60

    u64 accf2[4][4], accb2[4][4];
    const u64 z2 = pk2(0.f, 0.f);
#pragma unroll
    for (int i = 0; i < 4; i++)
#pragma unroll
        for (int j = 0; j < 4; j++) { accf2[i][j] = z2; accb2[i][j] = z2; }

    for (int e0 = 0; e0 < E_; e0 += 16) {
        float4 a0 = *(const float4*)(arow + e0 + lc);
        float4 a1 = *(const float4*)(arow + e0 + lc + 4);
        float4 f4 = *(const float4*)(Wf + (size_t)(e0 + bk) * H_ + j0 + bj);
        float4 b4 = *(const float4*)(Wb + (size_t)(e0 + bk) * H_ + j0 + bj);
        __syncthreads();
        As[lc + 0][lr] = a0.x; As[lc + 1][lr] = a0.y;
        As[lc + 2][lr] = a0.z; As[lc + 3][lr] = a0.w;
        As[lc + 4][lr] = a1.x; As[lc + 5][lr] = a1.y;
        As[lc + 6][lr] = a1.z; As[lc + 7][lr] = a1.w;
        *(float4*)&Bfs[bk][bj] = f4;
        *(float4*)&Bbs[bk][bj] = b4;
        __syncthreads();
#pragma unroll
        for (int kk = 0; kk < 16; kk++) {
            u64 a2[4];
#pragma unroll
            for (int i2 = 0; i2 < 4; i2++) {
                float2 av = *(const float2*)&As[kk][rbase + 2 * i2];
                a2[i2] = pk2(av.x, av.y);
            }
            float4 fv = *(const float4*)&Bfs[kk][cbase];
            float4 bv = *(const float4*)&Bbs[kk][cbase];
            u64 f2[4], b2[4];
            f2[0] = pk2(fv.x, fv.x); f2[1] = pk2(fv.y, fv.y);
            f2[2] = pk2(fv.z, fv.z); f2[3] = pk2(fv.w, fv.w);
            b2[0] = pk2(bv.x, bv.x); b2[1] = pk2(bv.y, bv.y);
            b2[2] = pk2(bv.z, bv.z); b2[3] = pk2(bv.w, bv.w);
#pragma unroll
            for (int i2 = 0; i2 < 4; i2++)
#pragma unroll
                for (int j = 0; j < 4; j++) {
                    FMA2(accf2[i2][j], a2[i2], f2[j], accf2[i2][j]);
                    FMA2(accb2[i2][j], a2[i2], b2[j], accb2[i2][j]);
                }
        }
    }

    float acc_f[8][4], acc_b[8][4];
#pragma unroll
    for (int i2 = 0; i2 < 4; i2++)
#pragma unroll
        for (int j = 0; j < 4; j++) {
            upk2(accf2[i2][j], acc_f[2 * i2][j], acc_f[2 * i2 + 1][j]);
            upk2(accb2[i2][j], acc_b[2 * i2][j], acc_b[2 * i2 + 1][j]);
        }

#pragma unroll
    for (int i = 0; i < 8; i++) {
        const int m = m0 + rbase + i;
        const int t = m >> 6, b = m & 63;
        const int m2 = (T_ - 1 - t) * B_ + b;      // scan index slot for xb
        float4 vf, vb;
        vf.x = acc_f[i][0] + bfv[j0 + cbase + 0];
        vf.y = acc_f[i][1] + bfv[j0 + cbase + 1];
        vf.z = acc_f[i][2] + bfv[j0 + cbase + 2];
        vf.w = acc_f[i][3] + bfv[j0 + cbase + 3];
        vb.x = acc_b[i][0] + bbv[j0 + cbase + 0];
        vb.y = acc_b[i][1] + bbv[j0 + cbase + 1];
        vb.z = acc_b[i][2] + bbv[j0 + cbase + 2];
        vb.w = acc_b[i][3] + bbv[j0 + cbase + 3];
        *(float4*)&g_xf[(size_t)m  * H_ + j0 + cbase] = vf;
        *(float4*)&g_xb[(size_t)m2 * H_ + j0 + cbase] = vb;
    }
}

// ---------------------------------------------------------------------------
// Kernel 2: persistent per-(batch,direction) recurrent scan.
// Zero-MOV FFMA2 inner loop (conflict-free: h broadcast LDS.128, W tail
// lane-consecutive ulonglong2) + deep x prefetch (register ring, depth 4).
// ---------------------------------------------------------------------------
extern __shared__ float smem_scan[];

__global__ __launch_bounds__(256) void scan_kernel(
    const float* __restrict__ Whh_f,
    const float* __restrict__ Whh_b,
    float* __restrict__ out)
{
    float*      h_sh = smem_scan;                         // [2][256]
    ulonglong2* Wsh2 = (ulonglong2*)(smem_scan + 2 * H_); // [KSH2][256]

    const int t   = threadIdx.x;
    const int dir = blockIdx.x >> 6;    // 0 = fwd, 1 = bwd
    const int b   = blockIdx.x & 63;

    const float* W    = dir ? Whh_b : Whh_f;
    const float* xarr = dir ? g_xb  : g_xf;

    // register W pairs: wreg[p] = {W[2p][t], W[2p+1][t]}, k = 0..159
    u64 wreg[KREGP];
#pragma unroll
    for (int p = 0; p < KREGP; p++)
        wreg[p] = pk2(W[(size_t)(2 * p) * H_ + t], W[(size_t)(2 * p + 1) * H_ + t]);
    // shared W tail, pre-paired (lane-consecutive -> conflict-free)
    for (int r = 0; r < KSH2; r++) {
        ulonglong2 w;
        w.x = pk2(W[(size_t)(160 + 4 * r + 0) * H_ + t], W[(size_t)(160 + 4 * r + 1) * H_ + t]);
        w.y = pk2(W[(size_t)(160 + 4 * r + 2) * H_ + t], W[(size_t)(160 + 4 * r + 3) * H_ + t]);
        Wsh2[r * H_ + t] = w;
    }
    h_sh[t] = 0.f;
    __syncthreads();

    const float* xp = xarr + (size_t)b * H_ + t;  // step stride = B_*H_

    // x prefetch ring: xq[i] holds x for step s+i
    float xq[XPF];
#pragma unroll
    for (int i = 0; i < XPF; i++)
        xq[i] = (i < T_) ? xp[(size_t)i * (B_ * H_)] : 0.f;

    float hlast = 0.f;
    int p = 0;

    const u64 z2 = pk2(0.f, 0.f);

    for (int s = 0; s < T_; ++s) {
        float x_cur = xq[0];
        // rotate ring and issue load for s + XPF (arrives ~3 steps later)
#pragma unroll
        for (int i = 0; i < XPF - 1; i++) xq[i] = xq[i + 1];
        if (s + XPF < T_) xq[XPF - 1] = xp[(size_t)(s + XPF) * (B_ * H_)];

        const ulonglong2* hc2 = (const ulonglong2*)(h_sh + p * H_); // 16B-aligned
        u64 a0 = z2, a1 = z2, a2 = z2, a3 = z2;

        // register-resident W rows: k = 0..159 (40 broadcast LDS.128)
#pragma unroll
        for (int q = 0; q < 40; q++) {
            ulonglong2 hv = hc2[q];
            if (q & 1) {
                FMA2(a2, hv.x, wreg[2 * q + 0], a2);
                FMA2(a3, hv.y, wreg[2 * q + 1], a3);
            } else {
                FMA2(a0, hv.x, wreg[2 * q + 0], a0);
                FMA2(a1, hv.y, wreg[2 * q + 1], a1);
            }
        }
        // shared-resident W rows: k = 160..255
#pragma unroll
        for (int r = 0; r < KSH2; r++) {
            ulonglong2 hv = hc2[40 + r];
            ulonglong2 wv = Wsh2[r * H_ + t];
            FMA2(a0, hv.x, wv.x, a0);
            FMA2(a1, hv.y, wv.y, a1);
        }

        float l0, u0, l1, u1, l2, u2, l3, u3;
        upk2(a0, l0, u0); upk2(a1, l1, u1);
        upk2(a2, l2, u2); upk2(a3, l3, u3);
        float sum = ((l0 + u0) + (l1 + u1)) + ((l2 + u2) + (l3 + u3)) + x_cur;
        float hn = fast_tanh(sum);

        h_sh[(p ^ 1) * H_ + t] = hn;

        const int t_orig = dir ? (T_ - 1 - s) : s;
        g_h[((size_t)(t_orig * B_ + b)) * (2 * H_) + dir * H_ + t] = hn;

        hlast = hn;
        p ^= 1;
        __syncthreads();
    }

    out[(size_t)B_ * T_ * O_ + (size_t)dir * (B_ * H_) + (size_t)b * H_ + t] = hlast;
}

// ---------------------------------------------------------------------------
// Kernel 3: output GEMM (R3 version — float4 B loads + packs).
// ---------------------------------------------------------------------------
__global__ __launch_bounds__(256) void out_kernel(
    const float* __restrict__ Why, const float* __restrict__ byv,
    float* __restrict__ out)
{
    __shared__ float As[16][132];
    __shared__ float Bs[16][68];

    const int tid = threadIdx.x;
    const int m0 = blockIdx.y * 128;
    const int j0 = blockIdx.x * 64;

    const int rbase = (tid >> 4) * 8;
    const int cbase = (tid & 15) * 4;

    const int lr = tid >> 1;
    const int lc = (tid & 1) * 8;
    const float* arow = g_h + (size_t)(m0 + lr) * (2 * H_);

    const int bk = tid >> 4;
    const int bj = (tid & 15) * 4;

    u64 acc2[4][4];
    const u64 z2 = pk2(0.f, 0.f);
#pragma unroll
    for (int i = 0; i < 4; i++)
#pragma unroll
        for (int j = 0; j < 4; j++) acc2[i][j] = z2;

    for (int e0 = 0; e0 < 2 * H_; e0 += 16) {
        float4 a0 = *(const float4*)(arow + e0 + lc);
        float4 a1 = *(const float4*)(arow + e0 + lc + 4);
        float4 w4 = *(const float4*)(Why + (size_t)(e0 + bk) * O_ + j0 + bj);
        __syncthreads();
        As[lc + 0][lr] = a0.x; As[lc + 1][lr] = a0.y;
        As[lc + 2][lr] = a0.z; As[lc + 3][lr] = a0.w;
        As[lc + 4][lr] = a1.x; As[lc + 5][lr] = a1.y;
        As[lc + 6][lr] = a1.z; As[lc + 7][lr] = a1.w;
        *(float4*)&Bs[bk][bj] = w4;
        __syncthreads();
#pragma unroll
        for (int kk = 0; kk < 16; kk++) {
            u64 a2[4];
#pragma unroll
            for (int i2 = 0; i2 < 4; i2++) {
                float2 av = *(const float2*)&As[kk][rbase + 2 * i2];
                a2[i2] = pk2(av.x, av.y);
            }
            float4 wv = *(const float4*)&Bs[kk][cbase];
            u64 w2[4];
            w2[0] = pk2(wv.x, wv.x); w2[1] = pk2(wv.y, wv.y);
            w2[2] = pk2(wv.z, wv.z); w2[3] = pk2(wv.w, wv.w);
#pragma unroll
            for (int i2 = 0; i2 < 4; i2++)
#pragma unroll
                for (int j = 0; j < 4; j++)
                    FMA2(acc2[i2][j], a2[i2], w2[j], acc2[i2][j]);
        }
    }

    float acc[8][4];
#pragma unroll
    for (int i2 = 0; i2 < 4; i2++)
#pragma unroll
        for (int j = 0; j < 4; j++)
            upk2(acc2[i2][j], acc[2 * i2][j], acc[2 * i2 + 1][j]);

#pragma unroll
    for (int i = 0; i < 8; i++) {
        const int m = m0 + rbase + i;
        const int t = m >> 6, b = m & 63;
        float4 v;
        v.x = acc[i][0] + byv[j0 + cbase + 0];
        v.y = acc[i][1] + byv[j0 + cbase + 1];
        v.z = acc[i][2] + byv[j0 + cbase + 2];
        v.w = acc[i][3] + byv[j0 + cbase + 3];
        *(float4*)&out[((size_t)b * T_ + t) * O_ + j0 + cbase] = v;
    }
}

// ---------------------------------------------------------------------------
// launch
// ---------------------------------------------------------------------------
extern "C" void kernel_launch(void* const* d_in, const int* in_sizes, int n_in,
                              void* d_out, int out_size)
{
    const float* X    = (const float*)d_in[0];
    const float* Wxhf = (const float*)d_in[1];
    const float* Whhf = (const float*)d_in[2];
    const float* bf   = (const float*)d_in[3];
    const float* Wxhb = (const float*)d_in[4];
    const float* Whhb = (const float*)d_in[5];
    const float* bb   = (const float*)d_in[6];
    const float* Why  = (const float*)d_in[7];
    const float* by   = (const float*)d_in[8];
    float* out = (float*)d_out;

    cudaFuncSetAttribute(scan_kernel,
                         cudaFuncAttributeMaxDynamicSharedMemorySize,
                         (int)SMEM_SCAN);

    proj_kernel<<<dim3(4, 256), 256>>>(X, Wxhf, bf, Wxhb, bb);
    scan_kernel<<<128, 256, SMEM_SCAN>>>(Whhf, Whhb, out);
    out_kernel<<<dim3(4, 256), 256>>>(Why, by, out);
}